// round 10
// baseline (speedup 1.0000x reference)
#include <cuda_runtime.h>
#include <cstdint>

// out[n] = w_mp * sum_{e : dst[e]==n} ew[e] * x[src[e]]
// x: [N,32] f32, edge_index: [2,E] int32, ew: [E] f32, w_mp: [1] f32
//
// Two-launch pipeline: bucket-permute -> per-node register gather.
// Gather v3: unconditional record burst overlapped with count load,
// 8-edge unroll with dual accumulators (deep MLP), early counter reset.

#define N_MAX 120000
#define CAP   64          // Poisson(16): P(deg>=64) ~ 1e-19 per node
#define SPILL_MAX 4096

__device__ int g_cnt[N_MAX];                               // zero-init
__device__ unsigned long long g_rec[(size_t)N_MAX * CAP];  // (bits(ew)<<32)|src
__device__ int g_spill_cnt;                                // zero-init
__device__ int g_spill_dst[SPILL_MAX];
__device__ unsigned long long g_spill_rec[SPILL_MAX];

// ---------- K1: one-pass bucket permute (2 edges/thread) ----------
__device__ __forceinline__ void permute_one(int s, int d, float w) {
    int pos = atomicAdd(&g_cnt[d], 1);
    unsigned long long r =
        ((unsigned long long)__float_as_uint(w) << 32) | (unsigned)s;
    if (pos < CAP) {
        g_rec[(size_t)d * CAP + pos] = r;
    } else {
        int sp = atomicAdd(&g_spill_cnt, 1);
        if (sp < SPILL_MAX) { g_spill_dst[sp] = d; g_spill_rec[sp] = r; }
    }
}

__global__ __launch_bounds__(256)
void k_permute(const int* __restrict__ ei, const float* __restrict__ ew, int E) {
    int t = blockIdx.x * blockDim.x + threadIdx.x;
    int e = t * 2;
    if (e + 1 < E) {
        int2   s2 = __ldg(reinterpret_cast<const int2*>(ei + e));
        int2   d2 = __ldg(reinterpret_cast<const int2*>(ei + E + e));
        float2 w2 = __ldg(reinterpret_cast<const float2*>(ew + e));
        permute_one(s2.x, d2.x, w2.x);
        permute_one(s2.y, d2.y, w2.y);
    } else if (e < E) {
        permute_one(__ldg(&ei[e]), __ldg(&ei[E + e]), __ldg(&ew[e]));
    }
}

// ---------- K2: per-node gather, warp per node; resets counters ----------
__device__ __forceinline__ void gather_batch(
    const float* __restrict__ x, int lane, unsigned rlo, unsigned rhi,
    int m, float& acc0, float& acc1)
{
    const unsigned FULL = 0xffffffffu;
    int k = 0;
    for (; k + 8 <= m; k += 8) {
        int s0 = (int)__shfl_sync(FULL, rlo, k + 0);
        int s1 = (int)__shfl_sync(FULL, rlo, k + 1);
        int s2 = (int)__shfl_sync(FULL, rlo, k + 2);
        int s3 = (int)__shfl_sync(FULL, rlo, k + 3);
        int s4 = (int)__shfl_sync(FULL, rlo, k + 4);
        int s5 = (int)__shfl_sync(FULL, rlo, k + 5);
        int s6 = (int)__shfl_sync(FULL, rlo, k + 6);
        int s7 = (int)__shfl_sync(FULL, rlo, k + 7);
        float v0 = __ldg(x + (size_t)s0 * 32 + lane);
        float v1 = __ldg(x + (size_t)s1 * 32 + lane);
        float v2 = __ldg(x + (size_t)s2 * 32 + lane);
        float v3 = __ldg(x + (size_t)s3 * 32 + lane);
        float v4 = __ldg(x + (size_t)s4 * 32 + lane);
        float v5 = __ldg(x + (size_t)s5 * 32 + lane);
        float v6 = __ldg(x + (size_t)s6 * 32 + lane);
        float v7 = __ldg(x + (size_t)s7 * 32 + lane);
        float w0 = __uint_as_float(__shfl_sync(FULL, rhi, k + 0));
        float w1 = __uint_as_float(__shfl_sync(FULL, rhi, k + 1));
        float w2 = __uint_as_float(__shfl_sync(FULL, rhi, k + 2));
        float w3 = __uint_as_float(__shfl_sync(FULL, rhi, k + 3));
        float w4 = __uint_as_float(__shfl_sync(FULL, rhi, k + 4));
        float w5 = __uint_as_float(__shfl_sync(FULL, rhi, k + 5));
        float w6 = __uint_as_float(__shfl_sync(FULL, rhi, k + 6));
        float w7 = __uint_as_float(__shfl_sync(FULL, rhi, k + 7));
        acc0 = fmaf(w0, v0, acc0); acc1 = fmaf(w1, v1, acc1);
        acc0 = fmaf(w2, v2, acc0); acc1 = fmaf(w3, v3, acc1);
        acc0 = fmaf(w4, v4, acc0); acc1 = fmaf(w5, v5, acc1);
        acc0 = fmaf(w6, v6, acc0); acc1 = fmaf(w7, v7, acc1);
    }
    for (; k + 2 <= m; k += 2) {
        int   s0 = (int)__shfl_sync(FULL, rlo, k + 0);
        int   s1 = (int)__shfl_sync(FULL, rlo, k + 1);
        float v0 = __ldg(x + (size_t)s0 * 32 + lane);
        float v1 = __ldg(x + (size_t)s1 * 32 + lane);
        float w0 = __uint_as_float(__shfl_sync(FULL, rhi, k + 0));
        float w1 = __uint_as_float(__shfl_sync(FULL, rhi, k + 1));
        acc0 = fmaf(w0, v0, acc0); acc1 = fmaf(w1, v1, acc1);
    }
    if (k < m) {
        int   s0 = (int)__shfl_sync(FULL, rlo, k);
        float w0 = __uint_as_float(__shfl_sync(FULL, rhi, k));
        acc0 = fmaf(w0, __ldg(x + (size_t)s0 * 32 + lane), acc0);
    }
}

__global__ __launch_bounds__(256)
void k_gather(const float* __restrict__ x, const float* __restrict__ w_mp,
              float* __restrict__ out, int n) {
    int node = (blockIdx.x * blockDim.x + threadIdx.x) >> 5;
    if (node >= n) return;
    int lane = threadIdx.x & 31;    // lane = feature column

    const unsigned long long* rec = g_rec + (size_t)node * CAP;
    // Record burst issued in parallel with the count load (no serial chain;
    // static bucket memory is always readable — garbage slots never consumed).
    unsigned long long r0 = __ldg(&rec[lane]);
    int raw_cnt = __ldg(&g_cnt[node]);
    if (lane == 0) g_cnt[node] = 0;     // early reset (graph replay invariant)

    int cnt = raw_cnt > CAP ? CAP : raw_cnt;
    int m0 = cnt > 32 ? 32 : cnt;

    float acc0 = 0.f, acc1 = 0.f;
    gather_batch(x, lane, (unsigned)r0, (unsigned)(r0 >> 32), m0, acc0, acc1);

    if (cnt > 32) {                      // rare: P(deg>32 | lambda=16) ~ 2e-4
        unsigned long long r1 = __ldg(&rec[32 + lane]);
        gather_batch(x, lane, (unsigned)r1, (unsigned)(r1 >> 32), cnt - 32, acc0, acc1);
    }

    // Spill path (cold; practically never taken).
    if (raw_cnt > CAP) {
        int spills = g_spill_cnt; if (spills > SPILL_MAX) spills = SPILL_MAX;
        for (int i = 0; i < spills; i++) {
            if (g_spill_dst[i] == node) {
                unsigned long long r = g_spill_rec[i];
                float w  = __uint_as_float((unsigned)(r >> 32));
                int  src = (int)(unsigned)r;
                acc0 = fmaf(w, __ldg(x + (size_t)src * 32 + lane), acc0);
            }
        }
    }

    out[(size_t)node * 32 + lane] = (acc0 + acc1) * __ldg(w_mp);
    if (node == 0 && lane == 1) g_spill_cnt = 0;
}

// ---------- Fallback (proven round-4 path) ----------
__global__ void k_zero_out(float4* __restrict__ out, int n4) {
    int i = blockIdx.x * blockDim.x + threadIdx.x;
    if (i < n4) out[i] = make_float4(0.f, 0.f, 0.f, 0.f);
}

__global__ __launch_bounds__(256)
void k_scatter_atomic(const float* __restrict__ x, const int* __restrict__ ei,
                      const float* __restrict__ ew, const float* __restrict__ w_mp,
                      float* __restrict__ out, int E) {
    int tid = blockIdx.x * blockDim.x + threadIdx.x;
    int e = tid >> 3, c = tid & 7;
    if (e >= E) return;
    int s = __ldg(&ei[e]);
    int d = __ldg(&ei[E + e]);
    float w = __ldg(&ew[e]) * __ldg(w_mp);
    float4 v = __ldg(reinterpret_cast<const float4*>(x + (size_t)s * 32) + c);
    v.x *= w; v.y *= w; v.z *= w; v.w *= w;
    float* dst = out + (size_t)d * 32 + c * 4;
    asm volatile("red.global.add.v4.f32 [%0], {%1, %2, %3, %4};"
                 :: "l"(dst), "f"(v.x), "f"(v.y), "f"(v.z), "f"(v.w)
                 : "memory");
}

extern "C" void kernel_launch(void* const* d_in, const int* in_sizes, int n_in,
                              void* d_out, int out_size) {
    const float* x    = (const float*)d_in[0];
    const int*   ei   = (const int*)d_in[1];
    const float* ew   = (const float*)d_in[2];
    const float* w_mp = (const float*)d_in[3];
    float* out = (float*)d_out;

    int E = in_sizes[2];
    int n = out_size / 32;   // nodes

    if (n <= N_MAX) {
        int pt = (E + 1) / 2;                       // 2 edges per thread
        k_permute<<<(pt + 255) / 256, 256>>>(ei, ew, E);
        k_gather<<<(n * 32 + 255) / 256, 256>>>(x, w_mp, out, n);
    } else {
        int n4 = out_size / 4;
        k_zero_out<<<(n4 + 255) / 256, 256>>>((float4*)out, n4);
        long long threads = (long long)E * 8;
        k_scatter_atomic<<<(int)((threads + 255) / 256), 256>>>(x, ei, ew, w_mp, out, E);
    }
}